// round 4
// baseline (speedup 1.0000x reference)
#include <cuda_runtime.h>
#include <cstdint>

#define B_    96
#define NW    10
#define NTOK  144
#define CH    192
#define HEADS_ 6
#define DH    32

// GEMM tiling
#define BM 128
#define BN 64
#define BK 32
#define ASTR 36
#define BSTR 68

// attention smem strides (floats)
#define QKSTR 36    // q/k rows: 36 mod 32 = 4 -> conflict-free ldmatrix phases
#define VTSTR 148   // vT rows (d-major): 148 mod 32 = 20 -> conflict-free
#define SSTR  148   // S rows

// attention smem offsets (floats)
#define OFF_QB 0
#define OFF_QS (OFF_QB + NTOK * QKSTR)          // 5184
#define OFF_KB (OFF_QS + NTOK * QKSTR)          // 10368
#define OFF_KS (OFF_KB + NTOK * QKSTR)          // 15552
#define OFF_VTB (OFF_KS + NTOK * QKSTR)         // 20736
#define OFF_VTS (OFF_VTB + DH * VTSTR)          // 25472
#define OFF_S  (OFF_VTS + DH * VTSTR)           // 30208
#define OFF_RI (OFF_S + NTOK * SSTR)            // 51520
#define ATTN_SMEM_FLOATS (OFF_RI + NTOK)        // 51664
#define ATTN_SMEM_BYTES (ATTN_SMEM_FLOATS * 4)  // 206656

// Scratch
__device__ float g_qkv[(size_t)3 * B_ * NW * HEADS_ * NTOK * DH];
__device__ float g_att[(size_t)B_ * NW * NTOK * CH];
__device__ float g_bias[(size_t)NW * HEADS_ * NTOK * NTOK];   // ~5 MB

// ---------------------------------------------------------------------------
// helpers
// ---------------------------------------------------------------------------
__device__ __forceinline__ uint32_t smem_u32(const void* p) {
    uint32_t a;
    asm("{ .reg .u64 t; cvta.to.shared.u64 t, %1; cvt.u32.u64 %0, t; }"
        : "=r"(a) : "l"(p));
    return a;
}
__device__ __forceinline__ float f2tf32(float x) {
    uint32_t r;
    asm("cvt.rna.tf32.f32 %0, %1;" : "=r"(r) : "f"(x));
    return __uint_as_float(r);
}
__device__ __forceinline__ void ldmA(uint32_t a[4], uint32_t addr) {
    asm volatile("ldmatrix.sync.aligned.m8n8.x4.shared.b16 {%0,%1,%2,%3}, [%4];"
                 : "=r"(a[0]), "=r"(a[1]), "=r"(a[2]), "=r"(a[3]) : "r"(addr));
}
__device__ __forceinline__ void mma_tf32(float c[4], const uint32_t a[4],
                                         uint32_t b0, uint32_t b1) {
    asm volatile(
        "mma.sync.aligned.m16n8k8.row.col.f32.tf32.tf32.f32 "
        "{%0,%1,%2,%3},{%4,%5,%6,%7},{%8,%9},{%0,%1,%2,%3};"
        : "+f"(c[0]), "+f"(c[1]), "+f"(c[2]), "+f"(c[3])
        : "r"(a[0]), "r"(a[1]), "r"(a[2]), "r"(a[3]), "r"(b0), "r"(b1));
}

// ---------------------------------------------------------------------------
// tf32 tensor-core GEMM mainloop (identical to R3)
// ---------------------------------------------------------------------------
template <int LDW>
__device__ __forceinline__ void gemm_tf32_main(
    const float* __restrict__ A, const float* __restrict__ W,
    int row0, int col0, float* As, float* Bs, float acc[2][4][4])
{
    int tid  = threadIdx.x;
    int warp = tid >> 5, lane = tid & 31;
    int wr = warp >> 1, wc = warp & 1;
    int nbase = wc * 32;
    int g = lane >> 2, la3 = lane & 3;

    int a_row = wr * 32 + (lane & 15);
    int a_cs  = (lane >> 4) * 4;
    uint32_t aAddr0 = smem_u32(&As[a_row * ASTR + a_cs]);
    uint32_t aAddr1 = smem_u32(&As[(a_row + 16) * ASTR + a_cs]);

    for (int k0 = 0; k0 < CH; k0 += BK) {
#pragma unroll
        for (int l = 0; l < 4; l++) {
            int idx = tid + l * 256;
            int r = idx >> 3, c4 = (idx & 7) << 2;
            float4 v = *(const float4*)(A + (size_t)(row0 + r) * CH + k0 + c4);
            v.x = f2tf32(v.x); v.y = f2tf32(v.y);
            v.z = f2tf32(v.z); v.w = f2tf32(v.w);
            *(float4*)&As[r * ASTR + c4] = v;
        }
#pragma unroll
        for (int l = 0; l < 2; l++) {
            int idx = tid + l * 256;
            int r = idx >> 4, c4 = (idx & 15) << 2;
            float4 v = *(const float4*)(W + (size_t)(k0 + r) * LDW + col0 + c4);
            v.x = f2tf32(v.x); v.y = f2tf32(v.y);
            v.z = f2tf32(v.z); v.w = f2tf32(v.w);
            *(float4*)&Bs[r * BSTR + c4] = v;
        }
        __syncthreads();

#pragma unroll
        for (int kc = 0; kc < BK; kc += 8) {
            uint32_t a0[4], a1[4];
            ldmA(a0, aAddr0 + kc * 4);
            ldmA(a1, aAddr1 + kc * 4);
            uint32_t b[4][2];
#pragma unroll
            for (int nr = 0; nr < 4; nr++) {
                int n = nbase + nr * 8 + g;
                b[nr][0] = __float_as_uint(Bs[(kc + la3) * BSTR + n]);
                b[nr][1] = __float_as_uint(Bs[(kc + 4 + la3) * BSTR + n]);
            }
#pragma unroll
            for (int nr = 0; nr < 4; nr++) {
                mma_tf32(acc[0][nr], a0, b[nr][0], b[nr][1]);
                mma_tf32(acc[1][nr], a1, b[nr][0], b[nr][1]);
            }
        }
        __syncthreads();
    }
}

__global__ __launch_bounds__(256) void qkv_gemm_mma(
    const float* __restrict__ A, const float* __restrict__ W,
    const float* __restrict__ bias)
{
    __shared__ float As[BM * ASTR];
    __shared__ float Bs[BK * BSTR];
    int row0 = blockIdx.y * BM;
    int col0 = blockIdx.x * BN;

    float acc[2][4][4];
#pragma unroll
    for (int m = 0; m < 2; m++)
#pragma unroll
        for (int n = 0; n < 4; n++)
#pragma unroll
            for (int j = 0; j < 4; j++) acc[m][n][j] = 0.f;

    gemm_tf32_main<576>(A, W, row0, col0, As, Bs, acc);

    int tid = threadIdx.x;
    int warp = tid >> 5, lane = tid & 31;
    int wr = warp >> 1, wc = warp & 1;
    int g = lane >> 2, la3 = lane & 3;

#pragma unroll
    for (int mr = 0; mr < 2; mr++) {
#pragma unroll
        for (int nr = 0; nr < 4; nr++) {
#pragma unroll
            for (int j = 0; j < 4; j++) {
                int row = row0 + wr * 32 + mr * 16 + g + ((j >> 1) << 3);
                int n   = col0 + wc * 32 + nr * 8 + la3 * 2 + (j & 1);
                float v = acc[mr][nr][j] + bias[n];
                int bw = row / NTOK, rr = row - bw * NTOK;
                int t = n / CH, rem = n - t * CH;
                int h = rem >> 5, d = rem & 31;
                g_qkv[((((size_t)t * (B_ * NW) + bw) * HEADS_ + h) * NTOK + rr) * DH + d] = v;
            }
        }
    }
}

__global__ __launch_bounds__(256) void proj_gemm_mma(
    const float* __restrict__ W, const float* __restrict__ bias,
    float* __restrict__ out)
{
    __shared__ float As[BM * ASTR];
    __shared__ float Bs[BK * BSTR];
    int row0 = blockIdx.y * BM;
    int col0 = blockIdx.x * BN;

    float acc[2][4][4];
#pragma unroll
    for (int m = 0; m < 2; m++)
#pragma unroll
        for (int n = 0; n < 4; n++)
#pragma unroll
            for (int j = 0; j < 4; j++) acc[m][n][j] = 0.f;

    gemm_tf32_main<CH>(g_att, W, row0, col0, As, Bs, acc);

    int tid = threadIdx.x;
    int warp = tid >> 5, lane = tid & 31;
    int wr = warp >> 1, wc = warp & 1;
    int g = lane >> 2, la3 = lane & 3;

#pragma unroll
    for (int mr = 0; mr < 2; mr++) {
#pragma unroll
        for (int nr = 0; nr < 4; nr++) {
#pragma unroll
            for (int j = 0; j < 4; j++) {
                int row = row0 + wr * 32 + mr * 16 + g + ((j >> 1) << 3);
                int n   = col0 + wc * 32 + nr * 8 + la3 * 2 + (j & 1);
                out[(size_t)row * CH + n] = acc[mr][nr][j] + bias[n];
            }
        }
    }
}

// ---------------------------------------------------------------------------
// Precompute g_bias[w][h][i][j] = bias_table[pidx[i*144+j]][w][h]
// ---------------------------------------------------------------------------
__global__ __launch_bounds__(256) void bias_precompute_kernel(
    const float* __restrict__ bias_table, const int* __restrict__ pidx)
{
    int wh = blockIdx.x;            // 0..59
    int w = wh / HEADS_, h = wh % HEADS_;
    float* dst = g_bias + (size_t)wh * (NTOK * NTOK);
    for (int idx = threadIdx.x; idx < NTOK * NTOK; idx += 256) {
        int p = pidx[idx];
        dst[idx] = bias_table[(p * NW + w) * HEADS_ + h];
    }
}

// ---------------------------------------------------------------------------
// Attention: one CTA per (b,w,h), 9 warps. Warp w owns rows [16w, 16w+16):
//   QK^T (3xTF32 mma) -> S smem -> softmax (bias+mask fused, exp stored tf32)
//   -> P@V (2xTF32 mma, vT layout) -> g_att.  No inter-warp sync after load.
// ---------------------------------------------------------------------------
__global__ __launch_bounds__(288, 1) void attn_mma_kernel(
    const float* __restrict__ mask)
{
    extern __shared__ float sm[];
    float* qb  = sm + OFF_QB;
    float* qs  = sm + OFF_QS;
    float* kb  = sm + OFF_KB;
    float* ks  = sm + OFF_KS;
    float* vtb = sm + OFF_VTB;
    float* vts = sm + OFF_VTS;
    float* S   = sm + OFF_S;
    float* ri  = sm + OFF_RI;

    int tid = threadIdx.x;
    int h = blockIdx.x, w = blockIdx.y, b = blockIdx.z;

    size_t base = (((size_t)b * NW + w) * HEADS_ + h) * (NTOK * DH);
    const size_t seg = (size_t)(B_ * NW * HEADS_) * (NTOK * DH);
    const float* gq = g_qkv + base;
    const float* gk = gq + seg;
    const float* gv = gk + seg;

    // ---- load + split into big/small tf32 halves ----
    for (int idx = tid; idx < NTOK * DH; idx += 288) {
        int r = idx >> 5, c = idx & 31;
        float x = gq[idx];
        float xb = f2tf32(x);
        qb[r * QKSTR + c] = xb;
        qs[r * QKSTR + c] = f2tf32(x - xb);
        float y = gk[idx];
        float yb = f2tf32(y);
        kb[r * QKSTR + c] = yb;
        ks[r * QKSTR + c] = f2tf32(y - yb);
        float z = gv[idx];
        float zb = f2tf32(z);
        vtb[c * VTSTR + r] = zb;          // transposed: [d][token]
        vts[c * VTSTR + r] = f2tf32(z - zb);
    }
    __syncthreads();

    int warp = tid >> 5, lane = tid & 31;
    int r0 = warp * 16;
    int g = lane >> 2, la3 = lane & 3;

    // ---- QK^T: acc[18][4] = S stripe [16 x 144] ----
    float acc[18][4];
#pragma unroll
    for (int t = 0; t < 18; t++)
#pragma unroll
        for (int j = 0; j < 4; j++) acc[t][j] = 0.f;

    // A-fragment lane addresses (Q)
    int a_row = r0 + (lane & 15);
    int a_cs  = (lane >> 4) * 4;
    uint32_t aQb = smem_u32(&qb[a_row * QKSTR + a_cs]);
    uint32_t aQs = smem_u32(&qs[a_row * QKSTR + a_cs]);
    // B-fragment lane base (K rows n, ldmatrix x4 covering 2 n-tiles x 2 k-halves)
    int b_row = (lane & 7) + ((lane >> 4) << 3);
    int b_cs  = ((lane >> 3) & 1) * 4;
    uint32_t bKb = smem_u32(&kb[b_row * QKSTR + b_cs]);
    uint32_t bKs = smem_u32(&ks[b_row * QKSTR + b_cs]);

#pragma unroll
    for (int kc = 0; kc < DH; kc += 8) {
        uint32_t aB[4], aS[4];
        ldmA(aB, aQb + kc * 4);
        ldmA(aS, aQs + kc * 4);
#pragma unroll
        for (int p = 0; p < 9; p++) {
            uint32_t rb[4], rs[4];
            uint32_t off = (uint32_t)(p * 16 * QKSTR + kc) * 4;
            ldmA(rb, bKb + off);
            ldmA(rs, bKs + off);
            // tile 2p: (b0,b1)=(rb[0],rb[1]); tile 2p+1: (rb[2],rb[3])
            mma_tf32(acc[2 * p],     aB, rb[0], rb[1]);
            mma_tf32(acc[2 * p],     aB, rs[0], rs[1]);
            mma_tf32(acc[2 * p],     aS, rb[0], rb[1]);
            mma_tf32(acc[2 * p + 1], aB, rb[2], rb[3]);
            mma_tf32(acc[2 * p + 1], aB, rs[2], rs[3]);
            mma_tf32(acc[2 * p + 1], aS, rb[2], rb[3]);
        }
    }

    // ---- store raw S stripe ----
#pragma unroll
    for (int t = 0; t < 18; t++) {
        int col = t * 8 + la3 * 2;
        *(float2*)&S[(r0 + g) * SSTR + col]     = make_float2(acc[t][0], acc[t][1]);
        *(float2*)&S[(r0 + g + 8) * SSTR + col] = make_float2(acc[t][2], acc[t][3]);
    }
    __syncwarp();

    // ---- softmax over own 16 rows (bias+mask fused; exp stored tf32) ----
    const float scale = 0.17677669529663687f;
    const float* biasW = g_bias + (size_t)(w * HEADS_ + h) * (NTOK * NTOK);
    const float* maskB = mask + (size_t)b * NTOK * NTOK;
    for (int r = r0; r < r0 + 16; r++) {
        float* Sr = S + r * SSTR;
        const float* br = biasW + r * NTOK;
        const float* mr = maskB + r * NTOK;
        float mx = -3.4e38f;
        for (int j = lane; j < NTOK; j += 32) {
            float t = Sr[j] * scale + br[j] + mr[j];
            Sr[j] = t;
            mx = fmaxf(mx, t);
        }
#pragma unroll
        for (int o = 16; o > 0; o >>= 1)
            mx = fmaxf(mx, __shfl_xor_sync(0xffffffffu, mx, o));
        float s = 0.f;
        for (int j = lane; j < NTOK; j += 32) {
            float e = f2tf32(__expf(Sr[j] - mx));
            Sr[j] = e;
            s += e;
        }
#pragma unroll
        for (int o = 16; o > 0; o >>= 1)
            s += __shfl_xor_sync(0xffffffffu, s, o);
        if (lane == 0) ri[r] = 1.f / s;
    }
    __syncwarp();

    // ---- O = P @ V : acc2[4][4] = O stripe [16 x 32] ----
    float acc2[4][4];
#pragma unroll
    for (int t = 0; t < 4; t++)
#pragma unroll
        for (int j = 0; j < 4; j++) acc2[t][j] = 0.f;

    uint32_t aP = smem_u32(&S[(r0 + (lane & 15)) * SSTR + (lane >> 4) * 4]);
    uint32_t bVb = smem_u32(&vtb[b_row * VTSTR + b_cs]);
    uint32_t bVs = smem_u32(&vts[b_row * VTSTR + b_cs]);

#pragma unroll
    for (int k2 = 0; k2 < 18; k2++) {
        uint32_t p[4];
        ldmA(p, aP + k2 * 32);             // 8 floats per k-step
#pragma unroll
        for (int p2 = 0; p2 < 2; p2++) {
            uint32_t rb[4], rs[4];
            uint32_t off = (uint32_t)(p2 * 16 * VTSTR + k2 * 8) * 4;
            ldmA(rb, bVb + off);
            ldmA(rs, bVs + off);
            mma_tf32(acc2[2 * p2],     p, rb[0], rb[1]);
            mma_tf32(acc2[2 * p2],     p, rs[0], rs[1]);
            mma_tf32(acc2[2 * p2 + 1], p, rb[2], rb[3]);
            mma_tf32(acc2[2 * p2 + 1], p, rs[2], rs[3]);
        }
    }

    // ---- write O with 1/rowsum ----
    float inv0 = ri[r0 + g];
    float inv1 = ri[r0 + g + 8];
    float* ob = g_att + (((size_t)b * NW + w) * NTOK) * CH + h * DH;
#pragma unroll
    for (int t = 0; t < 4; t++) {
        int d = t * 8 + la3 * 2;
        *(float2*)&ob[(size_t)(r0 + g) * CH + d] =
            make_float2(acc2[t][0] * inv0, acc2[t][1] * inv0);
        *(float2*)&ob[(size_t)(r0 + g + 8) * CH + d] =
            make_float2(acc2[t][2] * inv1, acc2[t][3] * inv1);
    }
}

// ---------------------------------------------------------------------------
extern "C" void kernel_launch(void* const* d_in, const int* in_sizes, int n_in,
                              void* d_out, int out_size)
{
    const float* x          = (const float*)d_in[0];
    const float* mask       = (const float*)d_in[1];
    const float* w_qkv      = (const float*)d_in[2];
    const float* b_qkv      = (const float*)d_in[3];
    const float* w_proj     = (const float*)d_in[4];
    const float* b_proj     = (const float*)d_in[5];
    const float* bias_table = (const float*)d_in[6];
    const int*   pidx       = (const int*)d_in[7];
    float* out = (float*)d_out;

    cudaFuncSetAttribute(attn_mma_kernel,
                         cudaFuncAttributeMaxDynamicSharedMemorySize,
                         ATTN_SMEM_BYTES);

    bias_precompute_kernel<<<NW * HEADS_, 256>>>(bias_table, pidx);
    qkv_gemm_mma<<<dim3(9, 1080), 256>>>(x, w_qkv, b_qkv);
    attn_mma_kernel<<<dim3(HEADS_, NW, B_), 288, ATTN_SMEM_BYTES>>>(mask);
    proj_gemm_mma<<<dim3(3, 1080), 256>>>(w_proj, b_proj, out);
}

// round 5
// speedup vs baseline: 1.0365x; 1.0365x over previous
#include <cuda_runtime.h>
#include <cstdint>

#define B_    96
#define NW    10
#define NTOK  144
#define CH    192
#define HEADS_ 6
#define DH    32

// GEMM tiling
#define BM 128
#define BN 64
#define BK 32
#define ASTR 36
#define BSTR 68

// attention smem strides (floats)
#define QKSTR 36
#define VTSTR 148
#define SSTR  148

// attention smem offsets (floats)
#define OFF_QB 0
#define OFF_QS (OFF_QB + NTOK * QKSTR)
#define OFF_KB (OFF_QS + NTOK * QKSTR)
#define OFF_KS (OFF_KB + NTOK * QKSTR)
#define OFF_VTB (OFF_KS + NTOK * QKSTR)
#define OFF_VTS (OFF_VTB + DH * VTSTR)
#define OFF_S  (OFF_VTS + DH * VTSTR)
#define OFF_RI (OFF_S + NTOK * SSTR)
#define ATTN_SMEM_FLOATS (OFF_RI + NTOK)
#define ATTN_SMEM_BYTES (ATTN_SMEM_FLOATS * 4)   // 206656

// Scratch
__device__ float g_qkv[(size_t)3 * B_ * NW * HEADS_ * NTOK * DH];
__device__ float g_att[(size_t)B_ * NW * NTOK * CH];
__device__ float g_bias[(size_t)NW * HEADS_ * NTOK * NTOK];

// ---------------------------------------------------------------------------
// helpers
// ---------------------------------------------------------------------------
__device__ __forceinline__ uint32_t smem_u32(const void* p) {
    uint32_t a;
    asm("{ .reg .u64 t; cvta.to.shared.u64 t, %1; cvt.u32.u64 %0, t; }"
        : "=r"(a) : "l"(p));
    return a;
}
__device__ __forceinline__ float f2tf32(float x) {
    uint32_t r;
    asm("cvt.rna.tf32.f32 %0, %1;" : "=r"(r) : "f"(x));
    return __uint_as_float(r);
}
__device__ __forceinline__ void ldmA(uint32_t a[4], uint32_t addr) {
    asm volatile("ldmatrix.sync.aligned.m8n8.x4.shared.b16 {%0,%1,%2,%3}, [%4];"
                 : "=r"(a[0]), "=r"(a[1]), "=r"(a[2]), "=r"(a[3]) : "r"(addr));
}
__device__ __forceinline__ void mma_tf32(float c[4], const uint32_t a[4],
                                         uint32_t b0, uint32_t b1) {
    asm volatile(
        "mma.sync.aligned.m16n8k8.row.col.f32.tf32.tf32.f32 "
        "{%0,%1,%2,%3},{%4,%5,%6,%7},{%8,%9},{%0,%1,%2,%3};"
        : "+f"(c[0]), "+f"(c[1]), "+f"(c[2]), "+f"(c[3])
        : "r"(a[0]), "r"(a[1]), "r"(a[2]), "r"(a[3]), "r"(b0), "r"(b1));
}
__device__ __forceinline__ void pair_bar(int id) {
    asm volatile("bar.sync %0, 64;" :: "r"(id) : "memory");
}

// ---------------------------------------------------------------------------
// tf32 tensor-core GEMM mainloop (unchanged)
// ---------------------------------------------------------------------------
template <int LDW>
__device__ __forceinline__ void gemm_tf32_main(
    const float* __restrict__ A, const float* __restrict__ W,
    int row0, int col0, float* As, float* Bs, float acc[2][4][4])
{
    int tid  = threadIdx.x;
    int warp = tid >> 5, lane = tid & 31;
    int wr = warp >> 1, wc = warp & 1;
    int nbase = wc * 32;
    int g = lane >> 2, la3 = lane & 3;

    int a_row = wr * 32 + (lane & 15);
    int a_cs  = (lane >> 4) * 4;
    uint32_t aAddr0 = smem_u32(&As[a_row * ASTR + a_cs]);
    uint32_t aAddr1 = smem_u32(&As[(a_row + 16) * ASTR + a_cs]);

    for (int k0 = 0; k0 < CH; k0 += BK) {
#pragma unroll
        for (int l = 0; l < 4; l++) {
            int idx = tid + l * 256;
            int r = idx >> 3, c4 = (idx & 7) << 2;
            float4 v = *(const float4*)(A + (size_t)(row0 + r) * CH + k0 + c4);
            v.x = f2tf32(v.x); v.y = f2tf32(v.y);
            v.z = f2tf32(v.z); v.w = f2tf32(v.w);
            *(float4*)&As[r * ASTR + c4] = v;
        }
#pragma unroll
        for (int l = 0; l < 2; l++) {
            int idx = tid + l * 256;
            int r = idx >> 4, c4 = (idx & 15) << 2;
            float4 v = *(const float4*)(W + (size_t)(k0 + r) * LDW + col0 + c4);
            v.x = f2tf32(v.x); v.y = f2tf32(v.y);
            v.z = f2tf32(v.z); v.w = f2tf32(v.w);
            *(float4*)&Bs[r * BSTR + c4] = v;
        }
        __syncthreads();

#pragma unroll
        for (int kc = 0; kc < BK; kc += 8) {
            uint32_t a0[4], a1[4];
            ldmA(a0, aAddr0 + kc * 4);
            ldmA(a1, aAddr1 + kc * 4);
            uint32_t b[4][2];
#pragma unroll
            for (int nr = 0; nr < 4; nr++) {
                int n = nbase + nr * 8 + g;
                b[nr][0] = __float_as_uint(Bs[(kc + la3) * BSTR + n]);
                b[nr][1] = __float_as_uint(Bs[(kc + 4 + la3) * BSTR + n]);
            }
#pragma unroll
            for (int nr = 0; nr < 4; nr++) {
                mma_tf32(acc[0][nr], a0, b[nr][0], b[nr][1]);
                mma_tf32(acc[1][nr], a1, b[nr][0], b[nr][1]);
            }
        }
        __syncthreads();
    }
}

__global__ __launch_bounds__(256) void qkv_gemm_mma(
    const float* __restrict__ A, const float* __restrict__ W,
    const float* __restrict__ bias)
{
    __shared__ float As[BM * ASTR];
    __shared__ float Bs[BK * BSTR];
    int row0 = blockIdx.y * BM;
    int col0 = blockIdx.x * BN;

    float acc[2][4][4];
#pragma unroll
    for (int m = 0; m < 2; m++)
#pragma unroll
        for (int n = 0; n < 4; n++)
#pragma unroll
            for (int j = 0; j < 4; j++) acc[m][n][j] = 0.f;

    gemm_tf32_main<576>(A, W, row0, col0, As, Bs, acc);

    int tid = threadIdx.x;
    int warp = tid >> 5, lane = tid & 31;
    int wr = warp >> 1, wc = warp & 1;
    int g = lane >> 2, la3 = lane & 3;

#pragma unroll
    for (int mr = 0; mr < 2; mr++) {
#pragma unroll
        for (int nr = 0; nr < 4; nr++) {
#pragma unroll
            for (int j = 0; j < 4; j++) {
                int row = row0 + wr * 32 + mr * 16 + g + ((j >> 1) << 3);
                int n   = col0 + wc * 32 + nr * 8 + la3 * 2 + (j & 1);
                float v = acc[mr][nr][j] + bias[n];
                int bw = row / NTOK, rr = row - bw * NTOK;
                int t = n / CH, rem = n - t * CH;
                int h = rem >> 5, d = rem & 31;
                g_qkv[((((size_t)t * (B_ * NW) + bw) * HEADS_ + h) * NTOK + rr) * DH + d] = v;
            }
        }
    }
}

__global__ __launch_bounds__(256) void proj_gemm_mma(
    const float* __restrict__ W, const float* __restrict__ bias,
    float* __restrict__ out)
{
    __shared__ float As[BM * ASTR];
    __shared__ float Bs[BK * BSTR];
    int row0 = blockIdx.y * BM;
    int col0 = blockIdx.x * BN;

    float acc[2][4][4];
#pragma unroll
    for (int m = 0; m < 2; m++)
#pragma unroll
        for (int n = 0; n < 4; n++)
#pragma unroll
            for (int j = 0; j < 4; j++) acc[m][n][j] = 0.f;

    gemm_tf32_main<CH>(g_att, W, row0, col0, As, Bs, acc);

    int tid = threadIdx.x;
    int warp = tid >> 5, lane = tid & 31;
    int wr = warp >> 1, wc = warp & 1;
    int g = lane >> 2, la3 = lane & 3;

#pragma unroll
    for (int mr = 0; mr < 2; mr++) {
#pragma unroll
        for (int nr = 0; nr < 4; nr++) {
#pragma unroll
            for (int j = 0; j < 4; j++) {
                int row = row0 + wr * 32 + mr * 16 + g + ((j >> 1) << 3);
                int n   = col0 + wc * 32 + nr * 8 + la3 * 2 + (j & 1);
                out[(size_t)row * CH + n] = acc[mr][nr][j] + bias[n];
            }
        }
    }
}

__global__ __launch_bounds__(256) void bias_precompute_kernel(
    const float* __restrict__ bias_table, const int* __restrict__ pidx)
{
    int wh = blockIdx.x;
    int w = wh / HEADS_, h = wh % HEADS_;
    float* dst = g_bias + (size_t)wh * (NTOK * NTOK);
    for (int idx = threadIdx.x; idx < NTOK * NTOK; idx += 256) {
        int p = pidx[idx];
        dst[idx] = bias_table[(p * NW + w) * HEADS_ + h];
    }
}

// ---------------------------------------------------------------------------
// Attention: one CTA per (b,w,h), 18 warps. Warp pair (2i,2i+1) shares the
// 16-row stripe [16i,16i+16): QK^T split by S-columns (72 each), softmax split
// by rows (8 each), PV split by d-half (16 each). Pair sync via named barriers.
// ---------------------------------------------------------------------------
__global__ __launch_bounds__(576, 1) void attn_mma_kernel(
    const float* __restrict__ mask)
{
    extern __shared__ float sm[];
    float* qb  = sm + OFF_QB;
    float* qs  = sm + OFF_QS;
    float* kb  = sm + OFF_KB;
    float* ks  = sm + OFF_KS;
    float* vtb = sm + OFF_VTB;
    float* vts = sm + OFF_VTS;
    float* S   = sm + OFF_S;
    float* ri  = sm + OFF_RI;

    int tid = threadIdx.x;
    int h = blockIdx.x, w = blockIdx.y, b = blockIdx.z;

    size_t base = (((size_t)b * NW + w) * HEADS_ + h) * (NTOK * DH);
    const size_t seg = (size_t)(B_ * NW * HEADS_) * (NTOK * DH);
    const float* gq = g_qkv + base;
    const float* gk = gq + seg;
    const float* gv = gk + seg;

    // ---- load + tf32 big/small split ----
    for (int idx = tid; idx < NTOK * DH; idx += 576) {
        int r = idx >> 5, c = idx & 31;
        float x = gq[idx];
        float xb = f2tf32(x);
        qb[r * QKSTR + c] = xb;
        qs[r * QKSTR + c] = f2tf32(x - xb);
        float y = gk[idx];
        float yb = f2tf32(y);
        kb[r * QKSTR + c] = yb;
        ks[r * QKSTR + c] = f2tf32(y - yb);
        float z = gv[idx];
        float zb = f2tf32(z);
        vtb[c * VTSTR + r] = zb;
        vts[c * VTSTR + r] = f2tf32(z - zb);
    }
    __syncthreads();

    int warp = tid >> 5, lane = tid & 31;
    int stripe = warp >> 1, ph = warp & 1;
    int r0 = stripe * 16;
    int barid = 1 + stripe;
    int g = lane >> 2, la3 = lane & 3;

    // ---- QK^T: this warp covers S[r0:r0+16, 72*ph : 72*ph+72] ----
    float acc[9][4];
#pragma unroll
    for (int t = 0; t < 9; t++)
#pragma unroll
        for (int j = 0; j < 4; j++) acc[t][j] = 0.f;

    int a_row = r0 + (lane & 15);
    int a_cs  = (lane >> 4) * 4;
    uint32_t aQb = smem_u32(&qb[a_row * QKSTR + a_cs]);
    uint32_t aQs = smem_u32(&qs[a_row * QKSTR + a_cs]);
    int b_row = ph * 72 + (lane & 7) + ((lane >> 4) << 3);
    int b_cs  = ((lane >> 3) & 1) * 4;
    uint32_t bKb = smem_u32(&kb[b_row * QKSTR + b_cs]);
    uint32_t bKs = smem_u32(&ks[b_row * QKSTR + b_cs]);

#pragma unroll
    for (int kc = 0; kc < DH; kc += 8) {
        uint32_t aB[4], aS[4];
        ldmA(aB, aQb + kc * 4);
        ldmA(aS, aQs + kc * 4);
#pragma unroll
        for (int p = 0; p < 5; p++) {   // tile pairs (2p, 2p+1); p=4: second half discarded
            uint32_t rb[4], rs[4];
            uint32_t off = (uint32_t)(p * 16 * QKSTR + kc) * 4;
            ldmA(rb, bKb + off);
            ldmA(rs, bKs + off);
            mma_tf32(acc[2 * p], aB, rb[0], rb[1]);
            mma_tf32(acc[2 * p], aB, rs[0], rs[1]);
            mma_tf32(acc[2 * p], aS, rb[0], rb[1]);
            if (p < 4) {
                mma_tf32(acc[2 * p + 1], aB, rb[2], rb[3]);
                mma_tf32(acc[2 * p + 1], aB, rs[2], rs[3]);
                mma_tf32(acc[2 * p + 1], aS, rb[2], rb[3]);
            }
        }
    }

    // ---- store S stripe-half ----
#pragma unroll
    for (int t = 0; t < 9; t++) {
        int col = ph * 72 + t * 8 + la3 * 2;
        *(float2*)&S[(r0 + g) * SSTR + col]     = make_float2(acc[t][0], acc[t][1]);
        *(float2*)&S[(r0 + g + 8) * SSTR + col] = make_float2(acc[t][2], acc[t][3]);
    }
    pair_bar(barid);

    // ---- softmax: 8 rows per warp ----
    const float scale = 0.17677669529663687f;
    const float* biasW = g_bias + (size_t)(w * HEADS_ + h) * (NTOK * NTOK);
    const float* maskB = mask + (size_t)b * NTOK * NTOK;
    int rs0 = r0 + ph * 8;
    for (int r = rs0; r < rs0 + 8; r++) {
        float* Sr = S + r * SSTR;
        const float* br = biasW + r * NTOK;
        const float* mr = maskB + r * NTOK;
        float mx = -3.4e38f;
        for (int j = lane; j < NTOK; j += 32) {
            float t = Sr[j] * scale + br[j] + mr[j];
            Sr[j] = t;
            mx = fmaxf(mx, t);
        }
#pragma unroll
        for (int o = 16; o > 0; o >>= 1)
            mx = fmaxf(mx, __shfl_xor_sync(0xffffffffu, mx, o));
        float s = 0.f;
        for (int j = lane; j < NTOK; j += 32) {
            float e = f2tf32(__expf(Sr[j] - mx));
            Sr[j] = e;
            s += e;
        }
#pragma unroll
        for (int o = 16; o > 0; o >>= 1)
            s += __shfl_xor_sync(0xffffffffu, s, o);
        if (lane == 0) ri[r] = 1.f / s;
    }
    pair_bar(barid);

    // ---- O = P @ V, d-half = [16*ph, 16*ph+16) ----
    float acc2[2][4];
#pragma unroll
    for (int t = 0; t < 2; t++)
#pragma unroll
        for (int j = 0; j < 4; j++) acc2[t][j] = 0.f;

    uint32_t aP = smem_u32(&S[(r0 + (lane & 15)) * SSTR + (lane >> 4) * 4]);
    int v_row = ph * 16 + (lane & 7) + ((lane >> 4) << 3);
    uint32_t bVb = smem_u32(&vtb[v_row * VTSTR + b_cs]);
    uint32_t bVs = smem_u32(&vts[v_row * VTSTR + b_cs]);

#pragma unroll
    for (int k2 = 0; k2 < 18; k2++) {
        uint32_t p4[4];
        ldmA(p4, aP + k2 * 32);
        uint32_t rb[4], rs[4];
        uint32_t off = (uint32_t)k2 * 32;
        ldmA(rb, bVb + off);
        ldmA(rs, bVs + off);
        mma_tf32(acc2[0], p4, rb[0], rb[1]);
        mma_tf32(acc2[0], p4, rs[0], rs[1]);
        mma_tf32(acc2[1], p4, rb[2], rb[3]);
        mma_tf32(acc2[1], p4, rs[2], rs[3]);
    }

    float inv0 = ri[r0 + g];
    float inv1 = ri[r0 + g + 8];
    float* ob = g_att + (((size_t)b * NW + w) * NTOK) * CH + h * DH + ph * 16;
#pragma unroll
    for (int t = 0; t < 2; t++) {
        int d = t * 8 + la3 * 2;
        *(float2*)&ob[(size_t)(r0 + g) * CH + d] =
            make_float2(acc2[t][0] * inv0, acc2[t][1] * inv0);
        *(float2*)&ob[(size_t)(r0 + g + 8) * CH + d] =
            make_float2(acc2[t][2] * inv1, acc2[t][3] * inv1);
    }
}

// ---------------------------------------------------------------------------
extern "C" void kernel_launch(void* const* d_in, const int* in_sizes, int n_in,
                              void* d_out, int out_size)
{
    const float* x          = (const float*)d_in[0];
    const float* mask       = (const float*)d_in[1];
    const float* w_qkv      = (const float*)d_in[2];
    const float* b_qkv      = (const float*)d_in[3];
    const float* w_proj     = (const float*)d_in[4];
    const float* b_proj     = (const float*)d_in[5];
    const float* bias_table = (const float*)d_in[6];
    const int*   pidx       = (const int*)d_in[7];
    float* out = (float*)d_out;

    cudaFuncSetAttribute(attn_mma_kernel,
                         cudaFuncAttributeMaxDynamicSharedMemorySize,
                         ATTN_SMEM_BYTES);

    bias_precompute_kernel<<<NW * HEADS_, 256>>>(bias_table, pidx);
    qkv_gemm_mma<<<dim3(9, 1080), 256>>>(x, w_qkv, b_qkv);
    attn_mma_kernel<<<dim3(HEADS_, NW, B_), 576, ATTN_SMEM_BYTES>>>(mask);
    proj_gemm_mma<<<dim3(3, 1080), 256>>>(w_proj, b_proj, out);
}

// round 6
// speedup vs baseline: 2.4477x; 2.3615x over previous
#include <cuda_runtime.h>
#include <cstdint>

#define B_    96
#define NW    10
#define NTOK  144
#define CH    192
#define HEADS_ 6
#define DH    32

// dense GEMM tiling (unchanged)
#define BM 128
#define BN 64
#define BK 32
#define ASTR 36
#define BSTR 68

// attention smem (bf16 halves)
#define QKH 40     // q/k row stride in halves (80 B rows; 20-word stride -> conflict-free)
#define VTH 152    // vT row stride in halves (304 B rows; 76-word stride -> conflict-free)
#define BY_QH 0
#define BY_QL (BY_QH + NTOK * QKH * 2)   // 11520
#define BY_KH (BY_QL + NTOK * QKH * 2)   // 23040
#define BY_KL (BY_KH + NTOK * QKH * 2)   // 34560
#define BY_VH (BY_KL + NTOK * QKH * 2)   // 46080
#define BY_VL (BY_VH + DH * VTH * 2)     // 55808
#define ATTN_SMEM_BYTES (BY_VL + DH * VTH * 2)   // 65536

// Scratch
__device__ float g_qkv[(size_t)3 * B_ * NW * HEADS_ * NTOK * DH];
__device__ float g_att[(size_t)B_ * NW * NTOK * CH];
__device__ float g_bias[(size_t)NW * HEADS_ * NTOK * NTOK];

// ---------------------------------------------------------------------------
// helpers
// ---------------------------------------------------------------------------
__device__ __forceinline__ uint32_t smem_u32(const void* p) {
    uint32_t a;
    asm("{ .reg .u64 t; cvta.to.shared.u64 t, %1; cvt.u32.u64 %0, t; }"
        : "=r"(a) : "l"(p));
    return a;
}
__device__ __forceinline__ float f2tf32(float x) {
    uint32_t r;
    asm("cvt.rna.tf32.f32 %0, %1;" : "=r"(r) : "f"(x));
    return __uint_as_float(r);
}
__device__ __forceinline__ void ldmA(uint32_t a[4], uint32_t addr) {
    asm volatile("ldmatrix.sync.aligned.m8n8.x4.shared.b16 {%0,%1,%2,%3}, [%4];"
                 : "=r"(a[0]), "=r"(a[1]), "=r"(a[2]), "=r"(a[3]) : "r"(addr));
}
__device__ __forceinline__ void mma_tf32(float c[4], const uint32_t a[4],
                                         uint32_t b0, uint32_t b1) {
    asm volatile(
        "mma.sync.aligned.m16n8k8.row.col.f32.tf32.tf32.f32 "
        "{%0,%1,%2,%3},{%4,%5,%6,%7},{%8,%9},{%0,%1,%2,%3};"
        : "+f"(c[0]), "+f"(c[1]), "+f"(c[2]), "+f"(c[3])
        : "r"(a[0]), "r"(a[1]), "r"(a[2]), "r"(a[3]), "r"(b0), "r"(b1));
}
__device__ __forceinline__ void mma_bf16(float c[4], const uint32_t a[4],
                                         uint32_t b0, uint32_t b1) {
    asm volatile(
        "mma.sync.aligned.m16n8k16.row.col.f32.bf16.bf16.f32 "
        "{%0,%1,%2,%3},{%4,%5,%6,%7},{%8,%9},{%0,%1,%2,%3};"
        : "+f"(c[0]), "+f"(c[1]), "+f"(c[2]), "+f"(c[3])
        : "r"(a[0]), "r"(a[1]), "r"(a[2]), "r"(a[3]), "r"(b0), "r"(b1));
}
__device__ __forceinline__ uint16_t bf16rn(float x) {
    uint16_t r;
    asm("cvt.rn.bf16.f32 %0, %1;" : "=h"(r) : "f"(x));
    return r;
}
// pack (e0 -> low half, e1 -> high half), hi = truncated bf16 (exact split)
__device__ __forceinline__ uint32_t pack_hi(float e0, float e1) {
    return (__float_as_uint(e1) & 0xffff0000u) | (__float_as_uint(e0) >> 16);
}
__device__ __forceinline__ uint32_t pack_lo(float e0, float e1) {
    float h0 = __uint_as_float(__float_as_uint(e0) & 0xffff0000u);
    float h1 = __uint_as_float(__float_as_uint(e1) & 0xffff0000u);
    float l0 = e0 - h0, l1 = e1 - h1;
    uint32_t r;
    asm("cvt.rn.bf16x2.f32 %0, %1, %2;" : "=r"(r) : "f"(l1), "f"(l0));
    return r;
}

// ---------------------------------------------------------------------------
// tf32 tensor-core GEMM mainloop (unchanged from R3/R5)
// ---------------------------------------------------------------------------
template <int LDW>
__device__ __forceinline__ void gemm_tf32_main(
    const float* __restrict__ A, const float* __restrict__ W,
    int row0, int col0, float* As, float* Bs, float acc[2][4][4])
{
    int tid  = threadIdx.x;
    int warp = tid >> 5, lane = tid & 31;
    int wr = warp >> 1, wc = warp & 1;
    int nbase = wc * 32;
    int g = lane >> 2, la3 = lane & 3;

    int a_row = wr * 32 + (lane & 15);
    int a_cs  = (lane >> 4) * 4;
    uint32_t aAddr0 = smem_u32(&As[a_row * ASTR + a_cs]);
    uint32_t aAddr1 = smem_u32(&As[(a_row + 16) * ASTR + a_cs]);

    for (int k0 = 0; k0 < CH; k0 += BK) {
#pragma unroll
        for (int l = 0; l < 4; l++) {
            int idx = tid + l * 256;
            int r = idx >> 3, c4 = (idx & 7) << 2;
            float4 v = *(const float4*)(A + (size_t)(row0 + r) * CH + k0 + c4);
            v.x = f2tf32(v.x); v.y = f2tf32(v.y);
            v.z = f2tf32(v.z); v.w = f2tf32(v.w);
            *(float4*)&As[r * ASTR + c4] = v;
        }
#pragma unroll
        for (int l = 0; l < 2; l++) {
            int idx = tid + l * 256;
            int r = idx >> 4, c4 = (idx & 15) << 2;
            float4 v = *(const float4*)(W + (size_t)(k0 + r) * LDW + col0 + c4);
            v.x = f2tf32(v.x); v.y = f2tf32(v.y);
            v.z = f2tf32(v.z); v.w = f2tf32(v.w);
            *(float4*)&Bs[r * BSTR + c4] = v;
        }
        __syncthreads();

#pragma unroll
        for (int kc = 0; kc < BK; kc += 8) {
            uint32_t a0[4], a1[4];
            ldmA(a0, aAddr0 + kc * 4);
            ldmA(a1, aAddr1 + kc * 4);
            uint32_t b[4][2];
#pragma unroll
            for (int nr = 0; nr < 4; nr++) {
                int n = nbase + nr * 8 + g;
                b[nr][0] = __float_as_uint(Bs[(kc + la3) * BSTR + n]);
                b[nr][1] = __float_as_uint(Bs[(kc + 4 + la3) * BSTR + n]);
            }
#pragma unroll
            for (int nr = 0; nr < 4; nr++) {
                mma_tf32(acc[0][nr], a0, b[nr][0], b[nr][1]);
                mma_tf32(acc[1][nr], a1, b[nr][0], b[nr][1]);
            }
        }
        __syncthreads();
    }
}

__global__ __launch_bounds__(256) void qkv_gemm_mma(
    const float* __restrict__ A, const float* __restrict__ W,
    const float* __restrict__ bias)
{
    __shared__ float As[BM * ASTR];
    __shared__ float Bs[BK * BSTR];
    int row0 = blockIdx.y * BM;
    int col0 = blockIdx.x * BN;

    float acc[2][4][4];
#pragma unroll
    for (int m = 0; m < 2; m++)
#pragma unroll
        for (int n = 0; n < 4; n++)
#pragma unroll
            for (int j = 0; j < 4; j++) acc[m][n][j] = 0.f;

    gemm_tf32_main<576>(A, W, row0, col0, As, Bs, acc);

    int tid = threadIdx.x;
    int warp = tid >> 5, lane = tid & 31;
    int wr = warp >> 1, wc = warp & 1;
    int g = lane >> 2, la3 = lane & 3;

#pragma unroll
    for (int mr = 0; mr < 2; mr++) {
#pragma unroll
        for (int nr = 0; nr < 4; nr++) {
#pragma unroll
            for (int j = 0; j < 4; j++) {
                int row = row0 + wr * 32 + mr * 16 + g + ((j >> 1) << 3);
                int n   = col0 + wc * 32 + nr * 8 + la3 * 2 + (j & 1);
                float v = acc[mr][nr][j] + bias[n];
                int bw = row / NTOK, rr = row - bw * NTOK;
                int t = n / CH, rem = n - t * CH;
                int h = rem >> 5, d = rem & 31;
                g_qkv[((((size_t)t * (B_ * NW) + bw) * HEADS_ + h) * NTOK + rr) * DH + d] = v;
            }
        }
    }
}

__global__ __launch_bounds__(256) void proj_gemm_mma(
    const float* __restrict__ W, const float* __restrict__ bias,
    float* __restrict__ out)
{
    __shared__ float As[BM * ASTR];
    __shared__ float Bs[BK * BSTR];
    int row0 = blockIdx.y * BM;
    int col0 = blockIdx.x * BN;

    float acc[2][4][4];
#pragma unroll
    for (int m = 0; m < 2; m++)
#pragma unroll
        for (int n = 0; n < 4; n++)
#pragma unroll
            for (int j = 0; j < 4; j++) acc[m][n][j] = 0.f;

    gemm_tf32_main<CH>(g_att, W, row0, col0, As, Bs, acc);

    int tid = threadIdx.x;
    int warp = tid >> 5, lane = tid & 31;
    int wr = warp >> 1, wc = warp & 1;
    int g = lane >> 2, la3 = lane & 3;

#pragma unroll
    for (int mr = 0; mr < 2; mr++) {
#pragma unroll
        for (int nr = 0; nr < 4; nr++) {
#pragma unroll
            for (int j = 0; j < 4; j++) {
                int row = row0 + wr * 32 + mr * 16 + g + ((j >> 1) << 3);
                int n   = col0 + wc * 32 + nr * 8 + la3 * 2 + (j & 1);
                out[(size_t)row * CH + n] = acc[mr][nr][j] + bias[n];
            }
        }
    }
}

__global__ __launch_bounds__(256) void bias_precompute_kernel(
    const float* __restrict__ bias_table, const int* __restrict__ pidx)
{
    int wh = blockIdx.x;
    int w = wh / HEADS_, h = wh % HEADS_;
    float* dst = g_bias + (size_t)wh * (NTOK * NTOK);
    for (int idx = threadIdx.x; idx < NTOK * NTOK; idx += 256) {
        int p = pidx[idx];
        dst[idx] = bias_table[(p * NW + w) * HEADS_ + h];
    }
}

// ---------------------------------------------------------------------------
// Attention: one CTA per (b,w,h), 9 warps (288 thr), 2 CTAs/SM.
// Warp i owns rows [16i,16i+16) end-to-end:
//   QK^T: bf16 hi/lo split mma (qh*kh + qh*kl + ql*kh), acc[18][4] = 16x144 S
//   softmax entirely in registers (quad shuffles), bias+mask fused
//   P repacked from acc regs into bf16 A-fragments (no smem round trip)
//   PV: bf16 split (ph*vh + ph*vl + pl*vh), 9 exact k16 chunks
// ---------------------------------------------------------------------------
__global__ __launch_bounds__(288, 2) void attn_mma_kernel(
    const float* __restrict__ mask)
{
    extern __shared__ char smc[];
    uint16_t* qh = (uint16_t*)(smc + BY_QH);
    uint16_t* ql = (uint16_t*)(smc + BY_QL);
    uint16_t* kh = (uint16_t*)(smc + BY_KH);
    uint16_t* kl = (uint16_t*)(smc + BY_KL);
    uint16_t* vh = (uint16_t*)(smc + BY_VH);
    uint16_t* vl = (uint16_t*)(smc + BY_VL);

    int tid = threadIdx.x;
    int h = blockIdx.x, w = blockIdx.y, b = blockIdx.z;

    size_t base = (((size_t)b * NW + w) * HEADS_ + h) * (NTOK * DH);
    const size_t seg = (size_t)(B_ * NW * HEADS_) * (NTOK * DH);
    const float* gq = g_qkv + base;
    const float* gk = gq + seg;
    const float* gv = gk + seg;

    // ---- load + bf16 hi/lo split (hi = truncation -> exact residual) ----
    for (int idx = tid; idx < NTOK * DH; idx += 288) {
        int r = idx >> 5, c = idx & 31;
        float x = gq[idx];
        uint32_t xb = __float_as_uint(x) & 0xffff0000u;
        qh[r * QKH + c] = (uint16_t)(xb >> 16);
        ql[r * QKH + c] = bf16rn(x - __uint_as_float(xb));
        float y = gk[idx];
        uint32_t yb = __float_as_uint(y) & 0xffff0000u;
        kh[r * QKH + c] = (uint16_t)(yb >> 16);
        kl[r * QKH + c] = bf16rn(y - __uint_as_float(yb));
        float z = gv[idx];
        uint32_t zb = __float_as_uint(z) & 0xffff0000u;
        vh[c * VTH + r] = (uint16_t)(zb >> 16);   // transposed [d][token]
        vl[c * VTH + r] = bf16rn(z - __uint_as_float(zb));
    }
    __syncthreads();

    int warp = tid >> 5, lane = tid & 31;
    int r0 = warp * 16;
    int g = lane >> 2, la3 = lane & 3;

    // ---- QK^T ----
    float acc[18][4];
#pragma unroll
    for (int t = 0; t < 18; t++)
#pragma unroll
        for (int j = 0; j < 4; j++) acc[t][j] = 0.f;

    uint32_t aQh = smem_u32(qh) + (uint32_t)(r0 + (lane & 15)) * (QKH * 2) + (lane >> 4) * 16;
    uint32_t aQl = smem_u32(ql) + (uint32_t)(r0 + (lane & 15)) * (QKH * 2) + (lane >> 4) * 16;
    uint32_t brw = (uint32_t)((lane & 7) + ((lane >> 4) << 3)) * (QKH * 2) + ((lane >> 3) & 1) * 16;
    uint32_t bKh = smem_u32(kh) + brw;
    uint32_t bKl = smem_u32(kl) + brw;

#pragma unroll
    for (int c = 0; c < 2; c++) {
        uint32_t ah[4], al[4];
        ldmA(ah, aQh + 32 * c);
        ldmA(al, aQl + 32 * c);
#pragma unroll
        for (int p = 0; p < 9; p++) {
            uint32_t bh4[4], bl4[4];
            uint32_t off = (uint32_t)(p * 16 * QKH * 2) + 32 * c;
            ldmA(bh4, bKh + off);
            ldmA(bl4, bKl + off);
            mma_bf16(acc[2 * p],     ah, bh4[0], bh4[1]);
            mma_bf16(acc[2 * p],     ah, bl4[0], bl4[1]);
            mma_bf16(acc[2 * p],     al, bh4[0], bh4[1]);
            mma_bf16(acc[2 * p + 1], ah, bh4[2], bh4[3]);
            mma_bf16(acc[2 * p + 1], ah, bl4[2], bl4[3]);
            mma_bf16(acc[2 * p + 1], al, bh4[2], bh4[3]);
        }
    }

    // ---- softmax in registers ----
    const float scale = 0.17677669529663687f;
    const float* biasW = g_bias + (size_t)(w * HEADS_ + h) * (NTOK * NTOK);
    const float* maskB = mask + (size_t)b * NTOK * NTOK;
    const float* bA = biasW + (r0 + g) * NTOK;
    const float* mA = maskB + (r0 + g) * NTOK;
    const float* bB = bA + 8 * NTOK;
    const float* mB = mA + 8 * NTOK;

    float mx0 = -3.4e38f, mx1 = -3.4e38f;
#pragma unroll
    for (int t = 0; t < 18; t++) {
        int col = t * 8 + 2 * la3;
        float2 bb = *(const float2*)(bA + col);
        float2 mm = *(const float2*)(mA + col);
        float2 bb2 = *(const float2*)(bB + col);
        float2 mm2 = *(const float2*)(mB + col);
        acc[t][0] = fmaf(acc[t][0], scale, bb.x + mm.x);
        acc[t][1] = fmaf(acc[t][1], scale, bb.y + mm.y);
        acc[t][2] = fmaf(acc[t][2], scale, bb2.x + mm2.x);
        acc[t][3] = fmaf(acc[t][3], scale, bb2.y + mm2.y);
        mx0 = fmaxf(mx0, fmaxf(acc[t][0], acc[t][1]));
        mx1 = fmaxf(mx1, fmaxf(acc[t][2], acc[t][3]));
    }
    mx0 = fmaxf(mx0, __shfl_xor_sync(0xffffffffu, mx0, 1));
    mx0 = fmaxf(mx0, __shfl_xor_sync(0xffffffffu, mx0, 2));
    mx1 = fmaxf(mx1, __shfl_xor_sync(0xffffffffu, mx1, 1));
    mx1 = fmaxf(mx1, __shfl_xor_sync(0xffffffffu, mx1, 2));

    float s0 = 0.f, s1 = 0.f;
#pragma unroll
    for (int t = 0; t < 18; t++) {
        acc[t][0] = __expf(acc[t][0] - mx0);
        acc[t][1] = __expf(acc[t][1] - mx0);
        acc[t][2] = __expf(acc[t][2] - mx1);
        acc[t][3] = __expf(acc[t][3] - mx1);
        s0 += acc[t][0] + acc[t][1];
        s1 += acc[t][2] + acc[t][3];
    }
    s0 += __shfl_xor_sync(0xffffffffu, s0, 1);
    s0 += __shfl_xor_sync(0xffffffffu, s0, 2);
    s1 += __shfl_xor_sync(0xffffffffu, s1, 1);
    s1 += __shfl_xor_sync(0xffffffffu, s1, 2);
    float inv0 = 1.f / s0;
    float inv1 = 1.f / s1;

    // ---- PV: P fragments repacked from acc, V from smem ----
    float o[4][4];
#pragma unroll
    for (int t = 0; t < 4; t++)
#pragma unroll
        for (int j = 0; j < 4; j++) o[t][j] = 0.f;

    uint32_t vrw = (uint32_t)((lane & 7) + ((lane >> 4) << 3)) * (VTH * 2) + ((lane >> 3) & 1) * 16;
    uint32_t bV0h = smem_u32(vh) + vrw;
    uint32_t bV0l = smem_u32(vl) + vrw;
    uint32_t bV1h = bV0h + 16 * VTH * 2;
    uint32_t bV1l = bV0l + 16 * VTH * 2;

#pragma unroll
    for (int c = 0; c < 9; c++) {
        uint32_t ah[4], al[4];
        ah[0] = pack_hi(acc[2 * c][0], acc[2 * c][1]);
        ah[1] = pack_hi(acc[2 * c][2], acc[2 * c][3]);
        ah[2] = pack_hi(acc[2 * c + 1][0], acc[2 * c + 1][1]);
        ah[3] = pack_hi(acc[2 * c + 1][2], acc[2 * c + 1][3]);
        al[0] = pack_lo(acc[2 * c][0], acc[2 * c][1]);
        al[1] = pack_lo(acc[2 * c][2], acc[2 * c][3]);
        al[2] = pack_lo(acc[2 * c + 1][0], acc[2 * c + 1][1]);
        al[3] = pack_lo(acc[2 * c + 1][2], acc[2 * c + 1][3]);

        uint32_t off = 32u * c;
        uint32_t v0h[4], v0l[4], v1h[4], v1l[4];
        ldmA(v0h, bV0h + off);
        ldmA(v0l, bV0l + off);
        ldmA(v1h, bV1h + off);
        ldmA(v1l, bV1l + off);

        mma_bf16(o[0], ah, v0h[0], v0h[1]);
        mma_bf16(o[0], ah, v0l[0], v0l[1]);
        mma_bf16(o[0], al, v0h[0], v0h[1]);
        mma_bf16(o[1], ah, v0h[2], v0h[3]);
        mma_bf16(o[1], ah, v0l[2], v0l[3]);
        mma_bf16(o[1], al, v0h[2], v0h[3]);
        mma_bf16(o[2], ah, v1h[0], v1h[1]);
        mma_bf16(o[2], ah, v1l[0], v1l[1]);
        mma_bf16(o[2], al, v1h[0], v1h[1]);
        mma_bf16(o[3], ah, v1h[2], v1h[3]);
        mma_bf16(o[3], ah, v1l[2], v1l[3]);
        mma_bf16(o[3], al, v1h[2], v1h[3]);
    }

    // ---- write O ----
    float* ob = g_att + (((size_t)b * NW + w) * NTOK) * CH + h * DH;
#pragma unroll
    for (int t = 0; t < 4; t++) {
        int d = t * 8 + 2 * la3;
        *(float2*)&ob[(size_t)(r0 + g) * CH + d] =
            make_float2(o[t][0] * inv0, o[t][1] * inv0);
        *(float2*)&ob[(size_t)(r0 + g + 8) * CH + d] =
            make_float2(o[t][2] * inv1, o[t][3] * inv1);
    }
}

// ---------------------------------------------------------------------------
extern "C" void kernel_launch(void* const* d_in, const int* in_sizes, int n_in,
                              void* d_out, int out_size)
{
    const float* x          = (const float*)d_in[0];
    const float* mask       = (const float*)d_in[1];
    const float* w_qkv      = (const float*)d_in[2];
    const float* b_qkv      = (const float*)d_in[3];
    const float* w_proj     = (const float*)d_in[4];
    const float* b_proj     = (const float*)d_in[5];
    const float* bias_table = (const float*)d_in[6];
    const int*   pidx       = (const int*)d_in[7];
    float* out = (float*)d_out;

    cudaFuncSetAttribute(attn_mma_kernel,
                         cudaFuncAttributeMaxDynamicSharedMemorySize,
                         ATTN_SMEM_BYTES);

    bias_precompute_kernel<<<NW * HEADS_, 256>>>(bias_table, pidx);
    qkv_gemm_mma<<<dim3(9, 1080), 256>>>(x, w_qkv, b_qkv);
    attn_mma_kernel<<<dim3(HEADS_, NW, B_), 288, ATTN_SMEM_BYTES>>>(mask);
    proj_gemm_mma<<<dim3(3, 1080), 256>>>(w_proj, b_proj, out);
}

// round 9
// speedup vs baseline: 2.5092x; 1.0251x over previous
#include <cuda_runtime.h>
#include <cstdint>

#define B_    96
#define NW    10
#define NTOK  144
#define CH    192
#define HEADS_ 6
#define DH    32

// dense GEMM tiling
#define BM 128
#define BN 64
#define BK 32
#define ASTR 36
#define BSTR 68
#define NSTAGE 3
#define AS_FLOATS (BM * ASTR)                     // 4608
#define BS_FLOATS (BK * BSTR)                     // 2176
#define STAGE_FLOATS (AS_FLOATS + BS_FLOATS)      // 6784
#define GEMM_SMEM_BYTES (NSTAGE * STAGE_FLOATS * 4)   // 81408
#define KITERS (CH / BK)                          // 6

// attention smem (bf16 halves)
#define QKH 40
#define VTH 152
#define BY_QH 0
#define BY_QL (BY_QH + NTOK * QKH * 2)
#define BY_KH (BY_QL + NTOK * QKH * 2)
#define BY_KL (BY_KH + NTOK * QKH * 2)
#define BY_VH (BY_KL + NTOK * QKH * 2)
#define BY_VL (BY_VH + DH * VTH * 2)
#define ATTN_SMEM_BYTES (BY_VL + DH * VTH * 2)   // 65536

// Scratch
__device__ float g_qkv[(size_t)3 * B_ * NW * HEADS_ * NTOK * DH];
__device__ float g_att[(size_t)B_ * NW * NTOK * CH];
__device__ float g_bias[(size_t)NW * HEADS_ * NTOK * NTOK];

// ---------------------------------------------------------------------------
// helpers
// ---------------------------------------------------------------------------
__device__ __forceinline__ uint32_t smem_u32(const void* p) {
    uint32_t a;
    asm("{ .reg .u64 t; cvta.to.shared.u64 t, %1; cvt.u32.u64 %0, t; }"
        : "=r"(a) : "l"(p));
    return a;
}
__device__ __forceinline__ void cvt_tf32_r(uint32_t& r) {
    asm("cvt.rna.tf32.f32 %0, %0;" : "+r"(r));
}
__device__ __forceinline__ uint32_t f2tf32_u(float x) {
    uint32_t r;
    asm("cvt.rna.tf32.f32 %0, %1;" : "=r"(r) : "f"(x));
    return r;
}
__device__ __forceinline__ void ldmA(uint32_t a[4], uint32_t addr) {
    asm volatile("ldmatrix.sync.aligned.m8n8.x4.shared.b16 {%0,%1,%2,%3}, [%4];"
                 : "=r"(a[0]), "=r"(a[1]), "=r"(a[2]), "=r"(a[3]) : "r"(addr));
}
__device__ __forceinline__ void mma_tf32(float c[4], const uint32_t a[4],
                                         uint32_t b0, uint32_t b1) {
    asm volatile(
        "mma.sync.aligned.m16n8k8.row.col.f32.tf32.tf32.f32 "
        "{%0,%1,%2,%3},{%4,%5,%6,%7},{%8,%9},{%0,%1,%2,%3};"
        : "+f"(c[0]), "+f"(c[1]), "+f"(c[2]), "+f"(c[3])
        : "r"(a[0]), "r"(a[1]), "r"(a[2]), "r"(a[3]), "r"(b0), "r"(b1));
}
__device__ __forceinline__ void mma_bf16(float c[4], const uint32_t a[4],
                                         uint32_t b0, uint32_t b1) {
    asm volatile(
        "mma.sync.aligned.m16n8k16.row.col.f32.bf16.bf16.f32 "
        "{%0,%1,%2,%3},{%4,%5,%6,%7},{%8,%9},{%0,%1,%2,%3};"
        : "+f"(c[0]), "+f"(c[1]), "+f"(c[2]), "+f"(c[3])
        : "r"(a[0]), "r"(a[1]), "r"(a[2]), "r"(a[3]), "r"(b0), "r"(b1));
}
__device__ __forceinline__ uint16_t bf16rn(float x) {
    uint16_t r;
    asm("cvt.rn.bf16.f32 %0, %1;" : "=h"(r) : "f"(x));
    return r;
}
__device__ __forceinline__ uint32_t pack_hi(float e0, float e1) {
    return (__float_as_uint(e1) & 0xffff0000u) | (__float_as_uint(e0) >> 16);
}
__device__ __forceinline__ uint32_t pack_lo(float e0, float e1) {
    float h0 = __uint_as_float(__float_as_uint(e0) & 0xffff0000u);
    float h1 = __uint_as_float(__float_as_uint(e1) & 0xffff0000u);
    float l0 = e0 - h0, l1 = e1 - h1;
    uint32_t r;
    asm("cvt.rn.bf16x2.f32 %0, %1, %2;" : "=r"(r) : "f"(l1), "f"(l0));
    return r;
}
__device__ __forceinline__ void cp_async16(uint32_t dst, const void* src) {
    asm volatile("cp.async.cg.shared.global [%0], [%1], 16;" :: "r"(dst), "l"(src));
}
__device__ __forceinline__ void cp_commit() {
    asm volatile("cp.async.commit_group;");
}
template <int N>
__device__ __forceinline__ void cp_wait() {
    asm volatile("cp.async.wait_group %0;" :: "n"(N));
}

// ---------------------------------------------------------------------------
// cp.async-pipelined tf32 GEMM mainloop
// acc += A[row0:+128, :CH] @ W[:CH, col0:+64].  A row-major [M,CH], W [CH,LDW].
// 256 threads, 8 warps (4x2), 32x32 warp tiles. 3-stage pipeline.
// tf32 rounding applied to fragments in registers (identical math to before).
// ---------------------------------------------------------------------------
template <int LDW>
__device__ __forceinline__ void gemm_tf32_pipe(
    const float* __restrict__ A, const float* __restrict__ W,
    int row0, int col0, float* smem, float acc[2][4][4])
{
    int tid  = threadIdx.x;
    int warp = tid >> 5, lane = tid & 31;
    int wr = warp >> 1, wc = warp & 1;
    int nbase = wc * 32;
    int g = lane >> 2, la3 = lane & 3;

    // per-thread fill coordinates
    int ar = tid >> 3, ac4 = (tid & 7) << 2;          // +l*32 rows
    int br = tid >> 4, bc4 = (tid & 15) << 2;         // +l*16 rows

    // per-thread ldmatrix A coordinates (within a stage buffer)
    int a_row = wr * 32 + (lane & 15);
    int a_cs  = (lane >> 4) * 4;

    uint32_t smem_base = smem_u32(smem);

    // ---- stage issue ----
    auto issue = [&](int s) {
        int buf = s % NSTAGE;
        int k0 = s * BK;
        uint32_t as = smem_base + (uint32_t)(buf * STAGE_FLOATS) * 4;
        uint32_t bs = as + AS_FLOATS * 4;
#pragma unroll
        for (int l = 0; l < 4; l++) {
            int r = ar + l * 32;
            cp_async16(as + (uint32_t)(r * ASTR + ac4) * 4,
                       A + (size_t)(row0 + r) * CH + k0 + ac4);
        }
#pragma unroll
        for (int l = 0; l < 2; l++) {
            int r = br + l * 16;
            cp_async16(bs + (uint32_t)(r * BSTR + bc4) * 4,
                       W + (size_t)(k0 + r) * LDW + col0 + bc4);
        }
        cp_commit();
    };

    issue(0);
    issue(1);

    for (int i = 0; i < KITERS; i++) {
        cp_wait<NSTAGE - 2>();
        __syncthreads();
        if (i + 2 < KITERS) issue(i + 2);

        int buf = i % NSTAGE;
        float* As = smem + buf * STAGE_FLOATS;
        float* Bs = As + AS_FLOATS;
        uint32_t aAddr0 = smem_u32(&As[a_row * ASTR + a_cs]);
        uint32_t aAddr1 = aAddr0 + 16 * ASTR * 4;

#pragma unroll
        for (int kc = 0; kc < BK; kc += 8) {
            uint32_t a0[4], a1[4];
            ldmA(a0, aAddr0 + kc * 4);
            ldmA(a1, aAddr1 + kc * 4);
#pragma unroll
            for (int j = 0; j < 4; j++) { cvt_tf32_r(a0[j]); cvt_tf32_r(a1[j]); }
            uint32_t b[4][2];
#pragma unroll
            for (int nr = 0; nr < 4; nr++) {
                int n = nbase + nr * 8 + g;
                b[nr][0] = f2tf32_u(Bs[(kc + la3) * BSTR + n]);
                b[nr][1] = f2tf32_u(Bs[(kc + 4 + la3) * BSTR + n]);
            }
#pragma unroll
            for (int nr = 0; nr < 4; nr++) {
                mma_tf32(acc[0][nr], a0, b[nr][0], b[nr][1]);
                mma_tf32(acc[1][nr], a1, b[nr][0], b[nr][1]);
            }
        }
    }
}

// ---------------------------------------------------------------------------
// GEMM1: qkv = x @ w_qkv + b_qkv, scatter into g_qkv [3,B,nW,H,N,Dh]
// ---------------------------------------------------------------------------
__global__ __launch_bounds__(256) void qkv_gemm_mma(
    const float* __restrict__ A, const float* __restrict__ W,
    const float* __restrict__ bias)
{
    extern __shared__ float gsm[];
    int row0 = blockIdx.y * BM;
    int col0 = blockIdx.x * BN;

    float acc[2][4][4];
#pragma unroll
    for (int m = 0; m < 2; m++)
#pragma unroll
        for (int n = 0; n < 4; n++)
#pragma unroll
            for (int j = 0; j < 4; j++) acc[m][n][j] = 0.f;

    gemm_tf32_pipe<576>(A, W, row0, col0, gsm, acc);

    int tid = threadIdx.x;
    int warp = tid >> 5, lane = tid & 31;
    int wr = warp >> 1, wc = warp & 1;
    int g = lane >> 2, la3 = lane & 3;

#pragma unroll
    for (int mr = 0; mr < 2; mr++) {
#pragma unroll
        for (int nr = 0; nr < 4; nr++) {
#pragma unroll
            for (int j = 0; j < 4; j++) {
                int row = row0 + wr * 32 + mr * 16 + g + ((j >> 1) << 3);
                int n   = col0 + wc * 32 + nr * 8 + la3 * 2 + (j & 1);
                float v = acc[mr][nr][j] + bias[n];
                int bw = row / NTOK, rr = row - bw * NTOK;
                int t = n / CH, rem = n - t * CH;
                int h = rem >> 5, d = rem & 31;
                g_qkv[((((size_t)t * (B_ * NW) + bw) * HEADS_ + h) * NTOK + rr) * DH + d] = v;
            }
        }
    }
}

// ---------------------------------------------------------------------------
// GEMM2: out = g_att @ w_proj + b_proj
// ---------------------------------------------------------------------------
__global__ __launch_bounds__(256) void proj_gemm_mma(
    const float* __restrict__ W, const float* __restrict__ bias,
    float* __restrict__ out)
{
    extern __shared__ float gsm[];
    int row0 = blockIdx.y * BM;
    int col0 = blockIdx.x * BN;

    float acc[2][4][4];
#pragma unroll
    for (int m = 0; m < 2; m++)
#pragma unroll
        for (int n = 0; n < 4; n++)
#pragma unroll
            for (int j = 0; j < 4; j++) acc[m][n][j] = 0.f;

    gemm_tf32_pipe<CH>(g_att, W, row0, col0, gsm, acc);

    int tid = threadIdx.x;
    int warp = tid >> 5, lane = tid & 31;
    int wr = warp >> 1, wc = warp & 1;
    int g = lane >> 2, la3 = lane & 3;

#pragma unroll
    for (int mr = 0; mr < 2; mr++) {
#pragma unroll
        for (int nr = 0; nr < 4; nr++) {
#pragma unroll
            for (int j = 0; j < 4; j++) {
                int row = row0 + wr * 32 + mr * 16 + g + ((j >> 1) << 3);
                int n   = col0 + wc * 32 + nr * 8 + la3 * 2 + (j & 1);
                out[(size_t)row * CH + n] = acc[mr][nr][j] + bias[n];
            }
        }
    }
}

__global__ __launch_bounds__(256) void bias_precompute_kernel(
    const float* __restrict__ bias_table, const int* __restrict__ pidx)
{
    int wh = blockIdx.x;
    int w = wh / HEADS_, h = wh % HEADS_;
    float* dst = g_bias + (size_t)wh * (NTOK * NTOK);
    for (int idx = threadIdx.x; idx < NTOK * NTOK; idx += 256) {
        int p = pidx[idx];
        dst[idx] = bias_table[(p * NW + w) * HEADS_ + h];
    }
}

// ---------------------------------------------------------------------------
// Attention (unchanged from R6): one CTA per (b,w,h), 9 warps, 2 CTAs/SM.
// ---------------------------------------------------------------------------
__global__ __launch_bounds__(288, 2) void attn_mma_kernel(
    const float* __restrict__ mask)
{
    extern __shared__ char smc[];
    uint16_t* qh = (uint16_t*)(smc + BY_QH);
    uint16_t* ql = (uint16_t*)(smc + BY_QL);
    uint16_t* kh = (uint16_t*)(smc + BY_KH);
    uint16_t* kl = (uint16_t*)(smc + BY_KL);
    uint16_t* vh = (uint16_t*)(smc + BY_VH);
    uint16_t* vl = (uint16_t*)(smc + BY_VL);

    int tid = threadIdx.x;
    int h = blockIdx.x, w = blockIdx.y, b = blockIdx.z;

    size_t base = (((size_t)b * NW + w) * HEADS_ + h) * (NTOK * DH);
    const size_t seg = (size_t)(B_ * NW * HEADS_) * (NTOK * DH);
    const float* gq = g_qkv + base;
    const float* gk = gq + seg;
    const float* gv = gk + seg;

    for (int idx = tid; idx < NTOK * DH; idx += 288) {
        int r = idx >> 5, c = idx & 31;
        float x = gq[idx];
        uint32_t xb = __float_as_uint(x) & 0xffff0000u;
        qh[r * QKH + c] = (uint16_t)(xb >> 16);
        ql[r * QKH + c] = bf16rn(x - __uint_as_float(xb));
        float y = gk[idx];
        uint32_t yb = __float_as_uint(y) & 0xffff0000u;
        kh[r * QKH + c] = (uint16_t)(yb >> 16);
        kl[r * QKH + c] = bf16rn(y - __uint_as_float(yb));
        float z = gv[idx];
        uint32_t zb = __float_as_uint(z) & 0xffff0000u;
        vh[c * VTH + r] = (uint16_t)(zb >> 16);
        vl[c * VTH + r] = bf16rn(z - __uint_as_float(zb));
    }
    __syncthreads();

    int warp = tid >> 5, lane = tid & 31;
    int r0 = warp * 16;
    int g = lane >> 2, la3 = lane & 3;

    float acc[18][4];
#pragma unroll
    for (int t = 0; t < 18; t++)
#pragma unroll
        for (int j = 0; j < 4; j++) acc[t][j] = 0.f;

    uint32_t aQh = smem_u32(qh) + (uint32_t)(r0 + (lane & 15)) * (QKH * 2) + (lane >> 4) * 16;
    uint32_t aQl = smem_u32(ql) + (uint32_t)(r0 + (lane & 15)) * (QKH * 2) + (lane >> 4) * 16;
    uint32_t brw = (uint32_t)((lane & 7) + ((lane >> 4) << 3)) * (QKH * 2) + ((lane >> 3) & 1) * 16;
    uint32_t bKh = smem_u32(kh) + brw;
    uint32_t bKl = smem_u32(kl) + brw;

#pragma unroll
    for (int c = 0; c < 2; c++) {
        uint32_t ah[4], al[4];
        ldmA(ah, aQh + 32 * c);
        ldmA(al, aQl + 32 * c);
#pragma unroll
        for (int p = 0; p < 9; p++) {
            uint32_t bh4[4], bl4[4];
            uint32_t off = (uint32_t)(p * 16 * QKH * 2) + 32 * c;
            ldmA(bh4, bKh + off);
            ldmA(bl4, bKl + off);
            mma_bf16(acc[2 * p],     ah, bh4[0], bh4[1]);
            mma_bf16(acc[2 * p],     ah, bl4[0], bl4[1]);
            mma_bf16(acc[2 * p],     al, bh4[0], bh4[1]);
            mma_bf16(acc[2 * p + 1], ah, bh4[2], bh4[3]);
            mma_bf16(acc[2 * p + 1], ah, bl4[2], bl4[3]);
            mma_bf16(acc[2 * p + 1], al, bh4[2], bh4[3]);
        }
    }

    const float scale = 0.17677669529663687f;
    const float* biasW = g_bias + (size_t)(w * HEADS_ + h) * (NTOK * NTOK);
    const float* maskB = mask + (size_t)b * NTOK * NTOK;
    const float* bA = biasW + (r0 + g) * NTOK;
    const float* mA = maskB + (r0 + g) * NTOK;
    const float* bB = bA + 8 * NTOK;
    const float* mB = mA + 8 * NTOK;

    float mx0 = -3.4e38f, mx1 = -3.4e38f;
#pragma unroll
    for (int t = 0; t < 18; t++) {
        int col = t * 8 + 2 * la3;
        float2 bb = *(const float2*)(bA + col);
        float2 mm = *(const float2*)(mA + col);
        float2 bb2 = *(const float2*)(bB + col);
        float2 mm2 = *(const float2*)(mB + col);
        acc[t][0] = fmaf(acc[t][0], scale, bb.x + mm.x);
        acc[t][1] = fmaf(acc[t][1], scale, bb.y + mm.y);
        acc[t][2] = fmaf(acc[t][2], scale, bb2.x + mm2.x);
        acc[t][3] = fmaf(acc[t][3], scale, bb2.y + mm2.y);
        mx0 = fmaxf(mx0, fmaxf(acc[t][0], acc[t][1]));
        mx1 = fmaxf(mx1, fmaxf(acc[t][2], acc[t][3]));
    }
    mx0 = fmaxf(mx0, __shfl_xor_sync(0xffffffffu, mx0, 1));
    mx0 = fmaxf(mx0, __shfl_xor_sync(0xffffffffu, mx0, 2));
    mx1 = fmaxf(mx1, __shfl_xor_sync(0xffffffffu, mx1, 1));
    mx1 = fmaxf(mx1, __shfl_xor_sync(0xffffffffu, mx1, 2));

    float s0 = 0.f, s1 = 0.f;
#pragma unroll
    for (int t = 0; t < 18; t++) {
        acc[t][0] = __expf(acc[t][0] - mx0);
        acc[t][1] = __expf(acc[t][1] - mx0);
        acc[t][2] = __expf(acc[t][2] - mx1);
        acc[t][3] = __expf(acc[t][3] - mx1);
        s0 += acc[t][0] + acc[t][1];
        s1 += acc[t][2] + acc[t][3];
    }
    s0 += __shfl_xor_sync(0xffffffffu, s0, 1);
    s0 += __shfl_xor_sync(0xffffffffu, s0, 2);
    s1 += __shfl_xor_sync(0xffffffffu, s1, 1);
    s1 += __shfl_xor_sync(0xffffffffu, s1, 2);
    float inv0 = 1.f / s0;
    float inv1 = 1.f / s1;

    float o[4][4];
#pragma unroll
    for (int t = 0; t < 4; t++)
#pragma unroll
        for (int j = 0; j < 4; j++) o[t][j] = 0.f;

    uint32_t vrw = (uint32_t)((lane & 7) + ((lane >> 4) << 3)) * (VTH * 2) + ((lane >> 3) & 1) * 16;
    uint32_t bV0h = smem_u32(vh) + vrw;
    uint32_t bV0l = smem_u32(vl) + vrw;
    uint32_t bV1h = bV0h + 16 * VTH * 2;
    uint32_t bV1l = bV0l + 16 * VTH * 2;

#pragma unroll
    for (int c = 0; c < 9; c++) {
        uint32_t ah[4], al[4];
        ah[0] = pack_hi(acc[2 * c][0], acc[2 * c][1]);
        ah[1] = pack_hi(acc[2 * c][2], acc[2 * c][3]);
        ah[2] = pack_hi(acc[2 * c + 1][0], acc[2 * c + 1][1]);
        ah[3] = pack_hi(acc[2 * c + 1][2], acc[2 * c + 1][3]);
        al[0] = pack_lo(acc[2 * c][0], acc[2 * c][1]);
        al[1] = pack_lo(acc[2 * c][2], acc[2 * c][3]);
        al[2] = pack_lo(acc[2 * c + 1][0], acc[2 * c + 1][1]);
        al[3] = pack_lo(acc[2 * c + 1][2], acc[2 * c + 1][3]);

        uint32_t off = 32u * c;
        uint32_t v0h[4], v0l[4], v1h[4], v1l[4];
        ldmA(v0h, bV0h + off);
        ldmA(v0l, bV0l + off);
        ldmA(v1h, bV1h + off);
        ldmA(v1l, bV1l + off);

        mma_bf16(o[0], ah, v0h[0], v0h[1]);
        mma_bf16(o[0], ah, v0l[0], v0l[1]);
        mma_bf16(o[0], al, v0h[0], v0h[1]);
        mma_bf16(o[1], ah, v0h[2], v0h[3]);
        mma_bf16(o[1], ah, v0l[2], v0l[3]);
        mma_bf16(o[1], al, v0h[2], v0h[3]);
        mma_bf16(o[2], ah, v1h[0], v1h[1]);
        mma_bf16(o[2], ah, v1l[0], v1l[1]);
        mma_bf16(o[2], al, v1h[0], v1h[1]);
        mma_bf16(o[3], ah, v1h[2], v1h[3]);
        mma_bf16(o[3], ah, v1l[2], v1l[3]);
        mma_bf16(o[3], al, v1h[2], v1h[3]);
    }

    float* ob = g_att + (((size_t)b * NW + w) * NTOK) * CH + h * DH;
#pragma unroll
    for (int t = 0; t < 4; t++) {
        int d = t * 8 + 2 * la3;
        *(float2*)&ob[(size_t)(r0 + g) * CH + d] =
            make_float2(o[t][0] * inv0, o[t][1] * inv0);
        *(float2*)&ob[(size_t)(r0 + g + 8) * CH + d] =
            make_float2(o[t][2] * inv1, o[t][3] * inv1);
    }
}

// ---------------------------------------------------------------------------
extern "C" void kernel_launch(void* const* d_in, const int* in_sizes, int n_in,
                              void* d_out, int out_size)
{
    const float* x          = (const float*)d_in[0];
    const float* mask       = (const float*)d_in[1];
    const float* w_qkv      = (const float*)d_in[2];
    const float* b_qkv      = (const float*)d_in[3];
    const float* w_proj     = (const float*)d_in[4];
    const float* b_proj     = (const float*)d_in[5];
    const float* bias_table = (const float*)d_in[6];
    const int*   pidx       = (const int*)d_in[7];
    float* out = (float*)d_out;

    cudaFuncSetAttribute(attn_mma_kernel,
                         cudaFuncAttributeMaxDynamicSharedMemorySize,
                         ATTN_SMEM_BYTES);
    cudaFuncSetAttribute(qkv_gemm_mma,
                         cudaFuncAttributeMaxDynamicSharedMemorySize,
                         GEMM_SMEM_BYTES);
    cudaFuncSetAttribute(proj_gemm_mma,
                         cudaFuncAttributeMaxDynamicSharedMemorySize,
                         GEMM_SMEM_BYTES);

    bias_precompute_kernel<<<NW * HEADS_, 256>>>(bias_table, pidx);
    qkv_gemm_mma<<<dim3(9, 1080), 256, GEMM_SMEM_BYTES>>>(x, w_qkv, b_qkv);
    attn_mma_kernel<<<dim3(HEADS_, NW, B_), 288, ATTN_SMEM_BYTES>>>(mask);
    proj_gemm_mma<<<dim3(3, 1080), 256, GEMM_SMEM_BYTES>>>(w_proj, b_proj, out);
}